// round 1
// baseline (speedup 1.0000x reference)
#include <cuda_runtime.h>
#include <cstdint>

// Problem constants
#define B_  8
#define K_  65536
#define C_  128
#define N_  1024
#define CL  8                 // cluster size (CTAs per batch)
#define PTS (K_/CL)           // 8192 points per CTA
#define TPB 1024
#define PPT (PTS/TPB)         // 8 points per thread

// Output layout: [ new_xyz (B,N,3) | new_features (B,C,N) | sample_inds (B,N) ], all float32
#define OXYZ  0
#define OFEAT (B_*N_*3)
#define OIND  (OFEAT + B_*C_*N_)

// Scratch for integer indices consumed by the gather kernel (no runtime alloc allowed)
__device__ int g_inds[B_*N_];

static __device__ __forceinline__ uint32_t cvta_s(const void* p){
  return (uint32_t)__cvta_generic_to_shared(p);
}
static __device__ __forceinline__ uint32_t mapa_rank(uint32_t a, uint32_t r){
  uint32_t o; asm("mapa.shared::cluster.u32 %0, %1, %2;" : "=r"(o) : "r"(a), "r"(r)); return o;
}
static __device__ __forceinline__ void mbar_init(uint32_t a, uint32_t cnt){
  asm volatile("mbarrier.init.shared.b64 [%0], %1;" :: "r"(a), "r"(cnt) : "memory");
}
static __device__ __forceinline__ void st_cl_f(uint32_t a, float v){
  asm volatile("st.shared::cluster.f32 [%0], %1;" :: "r"(a), "f"(v) : "memory");
}
static __device__ __forceinline__ void st_cl_u(uint32_t a, uint32_t v){
  asm volatile("st.shared::cluster.b32 [%0], %1;" :: "r"(a), "r"(v) : "memory");
}
static __device__ __forceinline__ void arrive_rel(uint32_t a){
  asm volatile("mbarrier.arrive.release.cluster.shared::cluster.b64 _, [%0];" :: "r"(a) : "memory");
}
static __device__ __forceinline__ void wait_par(uint32_t a, uint32_t ph){
  asm volatile(
    "{\n\t.reg .pred P1;\n\t"
    "W%=:\n\t"
    "mbarrier.try_wait.parity.acquire.cluster.shared::cta.b64 P1, [%0], %1, 0x989680;\n\t"
    "@P1 bra D%=;\n\t"
    "bra W%=;\n\t"
    "D%=:\n\t}"
    :: "r"(a), "r"(ph) : "memory");
}
static __device__ __forceinline__ void cluster_sync_(){
  asm volatile("barrier.cluster.arrive.aligned;" ::: "memory");
  asm volatile("barrier.cluster.wait.aligned;" ::: "memory");
}

// One cluster (8 CTAs) per batch. xyz + running min-dist live in registers.
// Per iteration: register-resident distance update + argmax (candidates carry
// coordinates), warp shuffle reduce -> smem -> warp0 reduce, candidate sent to
// leader CTA via DSMEM st + mbarrier arrive, leader picks global winner, writes
// outputs, and broadcasts winner coords back via DSMEM st + per-CTA mbarrier.
__global__ void __launch_bounds__(TPB,1) __cluster_dims__(CL,1,1)
fps_kernel(const float* __restrict__ xyz, float* __restrict__ out)
{
  __shared__ unsigned long long red_bar;    // leader: candidate collection (count CL)
  __shared__ unsigned long long bcast_bar;  // every CTA: winner broadcast (count 1)
  __shared__ float cur[3];                  // current farthest point coords
  __shared__ float cd[CL]; __shared__ int ci[CL];           // leader candidate slots
  __shared__ float cxs[CL], cys[CL], czs[CL];
  __shared__ float wdx[32]; __shared__ int wix[32];          // per-warp reduce slots
  __shared__ float wxx[32], wyx[32], wzx[32];

  const int tid  = threadIdx.x;
  const int b    = blockIdx.x / CL;
  const int rank = blockIdx.x % CL;
  const float* xb = xyz + (size_t)b * K_ * 3;

  if (tid == 0){
    mbar_init(cvta_s(&red_bar),  CL);
    mbar_init(cvta_s(&bcast_bar), 1);
    // First pick is index 0 (reference semantics)
    cur[0] = xb[0]; cur[1] = xb[1]; cur[2] = xb[2];
    if (rank == 0){
      size_t o = (size_t)b * N_;
      out[OXYZ + o*3 + 0] = cur[0];
      out[OXYZ + o*3 + 1] = cur[1];
      out[OXYZ + o*3 + 2] = cur[2];
      out[OIND + o] = 0.0f;
      g_inds[o] = 0;
    }
  }
  __syncthreads();
  cluster_sync_();   // mbarriers visible cluster-wide before any remote arrive

  // Load this thread's 8 points + init running distances (all registers)
  const int pbase = rank * PTS;
  float px[PPT], py[PPT], pz[PPT], dist[PPT];
#pragma unroll
  for (int j = 0; j < PPT; j++){
    int p = pbase + j*TPB + tid;
    px[j] = xb[3*p + 0];
    py[j] = xb[3*p + 1];
    pz[j] = xb[3*p + 2];
    dist[j] = 1e10f;
  }

  // Precompute remote addresses (tid0 only uses them)
  uint32_t s_cd=0, s_ci=0, s_cx=0, s_cy=0, s_cz=0, s_red=0;
  if (tid == 0){
    s_cd  = mapa_rank(cvta_s(&cd[rank]),  0);
    s_ci  = mapa_rank(cvta_s(&ci[rank]),  0);
    s_cx  = mapa_rank(cvta_s(&cxs[rank]), 0);
    s_cy  = mapa_rank(cvta_s(&cys[rank]), 0);
    s_cz  = mapa_rank(cvta_s(&czs[rank]), 0);
    s_red = mapa_rank(cvta_s(&red_bar),   0);
  }
  const uint32_t l_bcast = cvta_s(&bcast_bar);
  const uint32_t l_red   = cvta_s(&red_bar);
  const uint32_t l_cur   = cvta_s(&cur[0]);

  uint32_t phase = 0;
  for (int t = 1; t < N_; t++){
    const float cx = cur[0], cy = cur[1], cz = cur[2];

    // Distance update + local argmax. Strict '>' with ascending index scan
    // gives lowest-index-wins on ties (jnp.argmax first-occurrence).
    float bd = -1.0f; int bi = 0; float bx = 0.f, by = 0.f, bz = 0.f;
#pragma unroll
    for (int j = 0; j < PPT; j++){
      float dx = px[j] - cx, dy = py[j] - cy, dz = pz[j] - cz;
      // No FMA contraction: match unfused mul/add (dx^2 + dy^2) + dz^2
      float d = __fadd_rn(__fadd_rn(__fmul_rn(dx,dx), __fmul_rn(dy,dy)),
                          __fmul_rn(dz,dz));
      float nd = fminf(dist[j], d);
      dist[j] = nd;
      if (nd > bd){ bd = nd; bi = pbase + j*TPB + tid; bx = px[j]; by = py[j]; bz = pz[j]; }
    }

    // Warp butterfly reduce (carry coords with the candidate)
#pragma unroll
    for (int off = 16; off; off >>= 1){
      float od = __shfl_xor_sync(0xffffffffu, bd, off);
      int   oi = __shfl_xor_sync(0xffffffffu, bi, off);
      float ox = __shfl_xor_sync(0xffffffffu, bx, off);
      float oy = __shfl_xor_sync(0xffffffffu, by, off);
      float oz = __shfl_xor_sync(0xffffffffu, bz, off);
      if (od > bd || (od == bd && oi < bi)){ bd = od; bi = oi; bx = ox; by = oy; bz = oz; }
    }
    const int w = tid >> 5;
    if ((tid & 31) == 0){ wdx[w] = bd; wix[w] = bi; wxx[w] = bx; wyx[w] = by; wzx[w] = bz; }
    __syncthreads();

    if (w == 0){
      bd = wdx[tid]; bi = wix[tid]; bx = wxx[tid]; by = wyx[tid]; bz = wzx[tid];
#pragma unroll
      for (int off = 16; off; off >>= 1){
        float od = __shfl_xor_sync(0xffffffffu, bd, off);
        int   oi = __shfl_xor_sync(0xffffffffu, bi, off);
        float ox = __shfl_xor_sync(0xffffffffu, bx, off);
        float oy = __shfl_xor_sync(0xffffffffu, by, off);
        float oz = __shfl_xor_sync(0xffffffffu, bz, off);
        if (od > bd || (od == bd && oi < bi)){ bd = od; bi = oi; bx = ox; by = oy; bz = oz; }
      }
      if (tid == 0){
        // Ship CTA candidate to leader CTA slot, then arrive its collection bar
        st_cl_f(s_cd, bd);
        st_cl_u(s_ci, (uint32_t)bi);
        st_cl_f(s_cx, bx); st_cl_f(s_cy, by); st_cl_f(s_cz, bz);
        arrive_rel(s_red);
      }
    }

    if (rank == 0 && tid == 0){
      wait_par(l_red, phase);
      float Wd = -1.f; int Wi = 0; float Wx = 0.f, Wy = 0.f, Wz = 0.f;
#pragma unroll
      for (int r = 0; r < CL; r++){
        float d0 = cd[r]; int i0 = ci[r];
        if (d0 > Wd || (d0 == Wd && i0 < Wi)){
          Wd = d0; Wi = i0; Wx = cxs[r]; Wy = cys[r]; Wz = czs[r];
        }
      }
      size_t o = (size_t)b * N_ + t;
      out[OXYZ + o*3 + 0] = Wx;
      out[OXYZ + o*3 + 1] = Wy;
      out[OXYZ + o*3 + 2] = Wz;
      out[OIND + o] = (float)Wi;
      g_inds[o] = Wi;
      // Broadcast winner coords to every CTA + flip their bcast bars
#pragma unroll
      for (int r = 0; r < CL; r++){
        uint32_t c0 = mapa_rank(l_cur, r);
        st_cl_f(c0 + 0, Wx);
        st_cl_f(c0 + 4, Wy);
        st_cl_f(c0 + 8, Wz);
        arrive_rel(mapa_rank(l_bcast, r));
      }
    }

    wait_par(l_bcast, phase);
    phase ^= 1;
  }
  cluster_sync_();  // no CTA exits with remote ops possibly in flight
}

// Feature gather: out[b][c][t] = feat[b][c][ inds[b][t] ]
__global__ void gather_kernel(const float* __restrict__ feat, float* __restrict__ out)
{
  int i = blockIdx.x * blockDim.x + threadIdx.x;   // 0 .. B*C*N-1, layout b*C*N + c*N + t
  int t  = i & (N_ - 1);
  int bc = i >> 10;            // b*C + c
  int bb = bc >> 7;            // / C_
  int idx = g_inds[bb * N_ + t];
  out[OFEAT + i] = feat[(size_t)bc * K_ + idx];
}

extern "C" void kernel_launch(void* const* d_in, const int* in_sizes, int n_in,
                              void* d_out, int out_size)
{
  const float* xyz  = (const float*)d_in[0];   // (B,K,3)
  const float* feat = (const float*)d_in[1];   // (B,C,K)
  float* out = (float*)d_out;

  fps_kernel<<<B_ * CL, TPB>>>(xyz, out);
  gather_kernel<<<(B_ * C_ * N_) / 256, 256>>>(feat, out);
}

// round 2
// speedup vs baseline: 3.2651x; 3.2651x over previous
#include <cuda_runtime.h>
#include <cstdint>

// Problem constants
#define B_  8
#define K_  65536
#define C_  128
#define N_  1024
#define CL  8                 // CTAs (cluster) per batch
#define PTS (K_/CL)           // 8192 points per CTA
#define TPB 512
#define PPT (PTS/TPB)         // 16 points per thread
#define NW  (TPB/32)          // 16 warps

// Output layout: [ new_xyz (B,N,3) | new_features (B,C,N) | sample_inds (B,N) ], float32
#define OXYZ  0
#define OFEAT (B_*N_*3)
#define OIND  (OFEAT + B_*C_*N_)

__device__ int g_inds[B_*N_];

static __device__ __forceinline__ uint32_t cvta_s(const void* p){
  return (uint32_t)__cvta_generic_to_shared(p);
}
static __device__ __forceinline__ uint32_t mapa_rank(uint32_t a, uint32_t r){
  uint32_t o; asm("mapa.shared::cluster.u32 %0, %1, %2;" : "=r"(o) : "r"(a), "r"(r)); return o;
}
static __device__ __forceinline__ void mbar_init(uint32_t a, uint32_t cnt){
  asm volatile("mbarrier.init.shared.b64 [%0], %1;" :: "r"(a), "r"(cnt) : "memory");
}
static __device__ __forceinline__ void st_cl_f(uint32_t a, float v){
  asm volatile("st.shared::cluster.f32 [%0], %1;" :: "r"(a), "f"(v) : "memory");
}
static __device__ __forceinline__ void st_cl_u64(uint32_t a, unsigned long long v){
  asm volatile("st.shared::cluster.b64 [%0], %1;" :: "r"(a), "l"(v) : "memory");
}
static __device__ __forceinline__ void arrive_rel(uint32_t a){
  asm volatile("mbarrier.arrive.release.cluster.shared::cluster.b64 _, [%0];" :: "r"(a) : "memory");
}
static __device__ __forceinline__ void wait_par(uint32_t a, uint32_t ph){
  asm volatile(
    "{\n\t.reg .pred P1;\n\t"
    "W%=:\n\t"
    "mbarrier.try_wait.parity.acquire.cluster.shared::cta.b64 P1, [%0], %1, 0x989680;\n\t"
    "@P1 bra D%=;\n\t"
    "bra W%=;\n\t"
    "D%=:\n\t}"
    :: "r"(a), "r"(ph) : "memory");
}
static __device__ __forceinline__ void cluster_sync_(){
  asm volatile("barrier.cluster.arrive.aligned;" ::: "memory");
  asm volatile("barrier.cluster.wait.aligned;" ::: "memory");
}

static __device__ __forceinline__ unsigned long long bfly_max(unsigned long long best, int off){
  uint32_t lo = __shfl_xor_sync(0xffffffffu, (uint32_t)best, off);
  uint32_t hi = __shfl_xor_sync(0xffffffffu, (uint32_t)(best >> 32), off);
  unsigned long long o = ((unsigned long long)hi << 32) | lo;
  return (o > best) ? o : best;
}

// One 8-CTA cluster per batch. Points + running min-dist register-resident.
// Per iteration:
//   1) distance update + per-thread argmax (packed u64 key = distbits<<32 | ~idx)
//   2) warp butterfly on packed key, lane0 -> smem
//   3) __syncthreads; warp0 reduces 16 warp candidates (4 bfly levels on dup pattern)
//   4) warp0 lanes 0-7: all-to-all ship (key + coords from smem point copy) to every
//      CTA's double-buffered slots + arrive.release on that CTA's mbarrier (count 8)
//   5) warp0 waits its own mbarrier, reduces 8 slots (3 bfly levels), tid0 writes
//      winner to cur[] (+ global outputs on rank 0); __syncthreads releases all.
__global__ void __launch_bounds__(TPB,1) __cluster_dims__(CL,1,1)
fps_kernel(const float* __restrict__ xyz, float* __restrict__ out)
{
  extern __shared__ float spts[];                 // 3*PTS floats = 96KB (coords lookup)
  __shared__ unsigned long long bars[2];          // double-buffered mbarriers (count CL)
  __shared__ unsigned long long wcand[NW];        // per-warp candidates
  __shared__ unsigned long long sl_p[2][CL];      // per-source-CTA packed keys
  __shared__ float sl_x[2][CL], sl_y[2][CL], sl_z[2][CL];
  __shared__ float cur[3];                        // current farthest point coords

  const int tid  = threadIdx.x;
  const int lane = tid & 31;
  const int w    = tid >> 5;
  const int b    = blockIdx.x / CL;
  const int rank = blockIdx.x % CL;
  const float* xb = xyz + (size_t)b * K_ * 3;
  const int pbase = rank * PTS;

  if (tid == 0){
    mbar_init(cvta_s(&bars[0]), CL);
    mbar_init(cvta_s(&bars[1]), CL);
    if (rank == 0){
      size_t o = (size_t)b * N_;
      out[OXYZ + o*3 + 0] = xb[0];
      out[OXYZ + o*3 + 1] = xb[1];
      out[OXYZ + o*3 + 2] = xb[2];
      out[OIND + o] = 0.0f;
      g_inds[o] = 0;
    }
  }

  // smem copy of this CTA's points (for O(1) idx->coords lookup), coalesced
  for (int i = tid; i < 3*PTS; i += TPB) spts[i] = xb[pbase*3 + i];

  // register-resident points + running distances
  float px[PPT], py[PPT], pz[PPT], dist[PPT];
#pragma unroll
  for (int j = 0; j < PPT; j++){
    int p = pbase + j*TPB + tid;
    px[j] = xb[3*p + 0];
    py[j] = xb[3*p + 1];
    pz[j] = xb[3*p + 2];
    dist[j] = 1e10f;
  }
  float cx = xb[0], cy = xb[1], cz = xb[2];   // first pick = index 0

  __syncthreads();
  cluster_sync_();    // mbarriers visible cluster-wide before any remote arrive

  // warp0 lanes 0..7: remote addresses into CTA `lane`'s slots/bars
  uint32_t r_slp=0, r_slx=0, r_sly=0, r_slz=0, r_bar=0;
  if (w == 0 && lane < CL){
    r_slp = mapa_rank(cvta_s(&sl_p[0][rank]), (uint32_t)lane);
    r_slx = mapa_rank(cvta_s(&sl_x[0][rank]), (uint32_t)lane);
    r_sly = mapa_rank(cvta_s(&sl_y[0][rank]), (uint32_t)lane);
    r_slz = mapa_rank(cvta_s(&sl_z[0][rank]), (uint32_t)lane);
    r_bar = mapa_rank(cvta_s(&bars[0]),       (uint32_t)lane);
  }
  const uint32_t l_bar = cvta_s(&bars[0]);

  uint32_t ph0 = 0, ph1 = 0;
  for (int t = 1; t < N_; t++){
    const int buf = t & 1;

    // ---- 1) distance update (exact: unfused rn mul/add, matches reference) ----
#pragma unroll
    for (int j = 0; j < PPT; j++){
      float dx = px[j] - cx, dy = py[j] - cy, dz = pz[j] - cz;
      float d = __fadd_rn(__fadd_rn(__fmul_rn(dx,dx), __fmul_rn(dy,dy)),
                          __fmul_rn(dz,dz));
      dist[j] = fminf(dist[j], d);
    }
    // per-thread max + lowest-index-on-tie (scan high j -> low j, last write wins)
    float m = dist[0];
#pragma unroll
    for (int j = 1; j < PPT; j++) m = fmaxf(m, dist[j]);
    int loc = 0;
#pragma unroll
    for (int j = PPT-1; j >= 0; j--) if (dist[j] == m) loc = j*TPB + tid;
    // packed key: dist bits (>=0, order-monotonic) high, ~idx low (min idx wins)
    unsigned long long best =
      ((unsigned long long)__float_as_uint(m) << 32) | (uint32_t)~(uint32_t)(pbase + loc);

    // ---- 2) warp butterfly ----
#pragma unroll
    for (int off = 16; off; off >>= 1) best = bfly_max(best, off);
    if (lane == 0) wcand[w] = best;
    __syncthreads();

    // ---- 3/4/5) warp0: CTA reduce, all-to-all ship, wait, global reduce ----
    if (w == 0){
      best = wcand[lane & (NW-1)];          // 16 values duplicated across 32 lanes
#pragma unroll
      for (int off = 8; off; off >>= 1) best = bfly_max(best, off);

      uint32_t cidx = ~(uint32_t)best;      // CTA winner global index
      int lcl = (int)cidx - pbase;          // local to this CTA

      if (lane < CL){
        float X = spts[3*lcl + 0], Y = spts[3*lcl + 1], Z = spts[3*lcl + 2];
        uint32_t o64 = (uint32_t)buf * (CL*8);
        uint32_t o32 = (uint32_t)buf * (CL*4);
        st_cl_u64(r_slp + o64, best);
        st_cl_f  (r_slx + o32, X);
        st_cl_f  (r_sly + o32, Y);
        st_cl_f  (r_slz + o32, Z);
        arrive_rel(r_bar + (uint32_t)buf * 8);
      }

      // wait for all 8 CTA candidates, then reduce the 8 slots
      wait_par(l_bar + (uint32_t)buf * 8, buf ? ph1 : ph0);
      unsigned long long q = sl_p[buf][lane & (CL-1)];   // 8 values duplicated
#pragma unroll
      for (int off = 4; off; off >>= 1) q = bfly_max(q, off);

      uint32_t widx = ~(uint32_t)q;         // global winner index
      int s = (int)(widx >> 13);            // owning CTA rank (PTS = 8192)
      if (lane == 0){
        float X = sl_x[buf][s], Y = sl_y[buf][s], Z = sl_z[buf][s];
        cur[0] = X; cur[1] = Y; cur[2] = Z;
        if (rank == 0){
          size_t o = (size_t)b * N_ + t;
          out[OXYZ + o*3 + 0] = X;
          out[OXYZ + o*3 + 1] = Y;
          out[OXYZ + o*3 + 2] = Z;
          out[OIND + o] = (float)widx;
          g_inds[o] = (int)widx;
        }
      }
      if (buf) ph1 ^= 1; else ph0 ^= 1;
    }
    __syncthreads();
    cx = cur[0]; cy = cur[1]; cz = cur[2];
  }
  cluster_sync_();   // no CTA exits with remote traffic possibly in flight
}

// Feature gather: out[b][c][t] = feat[b][c][ inds[b][t] ]
__global__ void gather_kernel(const float* __restrict__ feat, float* __restrict__ out)
{
  int i = blockIdx.x * blockDim.x + threadIdx.x;   // b*C*N + c*N + t
  int t  = i & (N_ - 1);
  int bc = i >> 10;            // b*C + c
  int bb = bc >> 7;            // / C_
  int idx = g_inds[bb * N_ + t];
  out[OFEAT + i] = feat[(size_t)bc * K_ + idx];
}

extern "C" void kernel_launch(void* const* d_in, const int* in_sizes, int n_in,
                              void* d_out, int out_size)
{
  const float* xyz  = (const float*)d_in[0];   // (B,K,3)
  const float* feat = (const float*)d_in[1];   // (B,C,K)
  float* out = (float*)d_out;

  static int smem_set = 0;
  if (!smem_set){
    cudaFuncSetAttribute(fps_kernel, cudaFuncAttributeMaxDynamicSharedMemorySize,
                         3*PTS*(int)sizeof(float));
    smem_set = 1;
  }
  fps_kernel<<<B_ * CL, TPB, 3*PTS*sizeof(float)>>>(xyz, out);
  gather_kernel<<<(B_ * C_ * N_) / 256, 256>>>(feat, out);
}